// round 11
// baseline (speedup 1.0000x reference)
#include <cuda_runtime.h>
#include <cuda_fp16.h>

// Problem constants (shapes fixed by setup_inputs): B=2, H=W=256, D=128, C=4.
constexpr int   DVOX    = 128;
constexpr int   HPIX    = 256;
constexpr int   WPIX    = 256;
constexpr int   BBATCH  = 2;
constexpr float DT      = 0.03125f;            // 2^-5, EXACT power of two
constexpr int   NSTEPS  = 111;                 // ceil(2*sqrt(3)/DT) = 37 * 3
constexpr int   VOXELS  = DVOX * DVOX * DVOX;  // 2097152 per batch per channel

// 64 MB scratch: volume as fp16, x-pair duplicated:
// g_vol[b][z][y][x] = { c0..c3 @ x , c0..c3 @ x+1 }  (8 halves = 16 B, aligned)
// One LDG.128 fetches a full x-corner pair for all 4 channels.
__device__ uint4 g_vol[(size_t)BBATCH * VOXELS];

// ---------------------------------------------------------------------------
// Pass 1: fp16 convert + channel interleave + x-pair duplication.
// Moves 192 MB total -> already at HBM roofline (~23 us), compulsory traffic.
// ---------------------------------------------------------------------------
__global__ void __launch_bounds__(128)
interleave_kernel(const float* __restrict__ vol)
{
    __shared__ unsigned int s01[DVOX];   // half2(c0,c1) per x
    __shared__ unsigned int s23[DVOX];   // half2(c2,c3) per x

    int x   = threadIdx.x;
    int row = blockIdx.x;                        // flat over B * 128 * 128 rows
    int b   = row >> 14;                         // / (128*128)
    int zy  = row & (DVOX * DVOX - 1);

    const float* p = vol + (size_t)b * 4 * VOXELS + (size_t)zy * DVOX + x;
    __half2 a01 = __halves2half2(__float2half_rn(p[0]),
                                 __float2half_rn(p[VOXELS]));
    __half2 a23 = __halves2half2(__float2half_rn(p[2 * VOXELS]),
                                 __float2half_rn(p[3 * VOXELS]));
    s01[x] = *reinterpret_cast<unsigned int*>(&a01);
    s23[x] = *reinterpret_cast<unsigned int*>(&a23);
    __syncthreads();

    int x1 = (x < DVOX - 1) ? x + 1 : x;         // x=127 slot is never sampled
    uint4 u;
    u.x = s01[x];  u.y = s23[x];
    u.z = s01[x1]; u.w = s23[x1];
    g_vol[(size_t)b * VOXELS + (size_t)zy * DVOX + x] = u;
}

// ---------------------------------------------------------------------------
// half2 helpers
// ---------------------------------------------------------------------------
__device__ __forceinline__ __half2 H2(unsigned int u)
{
    return *reinterpret_cast<__half2*>(&u);
}
__device__ __forceinline__ __half2 h2lerp(__half2 a, __half2 b, __half2 t)
{
    return __hfma2(__hsub2(b, a), t, a);   // a + t*(b-a)
}

// Full-half2 trilinear sample: 4 corner-row regs (each holds {c@x, c@x+1} for
// 4 channels), fp16 frac weights, single fp32 conversion at the end.
__device__ __forceinline__ float4 trilerp(uint4 r00, uint4 r01,
                                          uint4 r10, uint4 r11,
                                          float ffx, float ffy, float ffz)
{
    __half2 fx = __float2half2_rn(ffx);
    __half2 fy = __float2half2_rn(ffy);
    __half2 fz = __float2half2_rn(ffz);

    __half2 x00a = h2lerp(H2(r00.x), H2(r00.z), fx);  // ch 0,1
    __half2 x00b = h2lerp(H2(r00.y), H2(r00.w), fx);  // ch 2,3
    __half2 x01a = h2lerp(H2(r01.x), H2(r01.z), fx);
    __half2 x01b = h2lerp(H2(r01.y), H2(r01.w), fx);
    __half2 x10a = h2lerp(H2(r10.x), H2(r10.z), fx);
    __half2 x10b = h2lerp(H2(r10.y), H2(r10.w), fx);
    __half2 x11a = h2lerp(H2(r11.x), H2(r11.z), fx);
    __half2 x11b = h2lerp(H2(r11.y), H2(r11.w), fx);

    __half2 y0a = h2lerp(x00a, x01a, fy);
    __half2 y0b = h2lerp(x00b, x01b, fy);
    __half2 y1a = h2lerp(x10a, x11a, fy);
    __half2 y1b = h2lerp(x10b, x11b, fy);

    __half2 za = h2lerp(y0a, y1a, fz);
    __half2 zb = h2lerp(y0b, y1b, fz);

    float2 f01 = __half22float2(za);
    float2 f23 = __half22float2(zb);
    return make_float4(f01.x, f01.y, f23.x, f23.y);
}

// Grid coord + cell index + frac. g = fma(pos, 63.5, 63.5) — continuous vs the
// reference's op chain (trilinear is continuous across cell flips), only the
// validity test (done on exact pos) is discrete. Integer clamp keeps the
// address in-bounds for gated-off (invalid) samples.
__device__ __forceinline__ void coord(float pos, int& i0, float& fr)
{
    float g = __fmaf_rn(pos, 63.5f, 63.5f);
    int i = (int)g;                 // trunc; g<0 only when invalid (gated off)
    i0 = min(max(i, 0), 126);
    fr = g - (float)i0;
}

// ---------------------------------------------------------------------------
// Pass 2: ray march, 3 steps per iteration (12 LDG.128 in flight; 111 = 37*3).
// Ray setup replicates XLA's un-contracted fp32 chain bit-exactly (first
// sample sits ON the z=-1 face; validity there is a 1-ulp knife edge).
// Validity gates contrib by multiply, exactly like the reference.
// ---------------------------------------------------------------------------
__global__ void __launch_bounds__(128)
raymarch_kernel(const float* __restrict__ camrot,
                const float* __restrict__ campos,
                const float* __restrict__ focal,
                const float* __restrict__ princpt,
                const float* __restrict__ pixelcoords,
                float* __restrict__ out)
{
    int idx = blockIdx.x * blockDim.x + threadIdx.x;   // flat over B*H*W
    int w = idx & (WPIX - 1);
    int h = (idx >> 8) & (HPIX - 1);
    int b = idx >> 16;

    float2 pc = reinterpret_cast<const float2*>(pixelcoords)[idx];

    float fx = focal[b * 2 + 0], fy = focal[b * 2 + 1];
    float px = princpt[b * 2 + 0], py = princpt[b * 2 + 1];

    // (pixel - princpt) / focal : rn sub, rn div (XLA: separate ops, no FMA)
    float rx = __fdiv_rn(__fsub_rn(pc.x, px), fx);
    float ry = __fdiv_rn(__fsub_rn(pc.y, py), fy);
    float rz = 1.0f;

    const float* R = camrot + b * 9;   // camrot^T applied
    float dx = __fadd_rn(__fadd_rn(__fmul_rn(R[0], rx), __fmul_rn(R[3], ry)),
                         __fmul_rn(R[6], rz));
    float dy = __fadd_rn(__fadd_rn(__fmul_rn(R[1], rx), __fmul_rn(R[4], ry)),
                         __fmul_rn(R[7], rz));
    float dz = __fadd_rn(__fadd_rn(__fmul_rn(R[2], rx), __fmul_rn(R[5], ry)),
                         __fmul_rn(R[8], rz));

    float s = __fadd_rn(__fadd_rn(__fmul_rn(dx, dx), __fmul_rn(dy, dy)),
                        __fmul_rn(dz, dz));
    float nrm = sqrtf(s);
    dx = __fdiv_rn(dx, nrm);
    dy = __fdiv_rn(dy, nrm);
    dz = __fdiv_rn(dz, nrm);

    float cx = campos[b * 3 + 0], cy = campos[b * 3 + 1], cz = campos[b * 3 + 2];

    float t1x = __fdiv_rn(__fsub_rn(-1.0f, cx), dx);
    float t2x = __fdiv_rn(__fsub_rn( 1.0f, cx), dx);
    float t1y = __fdiv_rn(__fsub_rn(-1.0f, cy), dy);
    float t2y = __fdiv_rn(__fsub_rn( 1.0f, cy), dy);
    float t1z = __fdiv_rn(__fsub_rn(-1.0f, cz), dz);
    float t2z = __fdiv_rn(__fsub_rn( 1.0f, cz), dz);
    float tmin = fmaxf(fminf(t1x, t2x),
                 fmaxf(fminf(t1y, t2y), fminf(t1z, t2z)));
    float tmax = fminf(fmaxf(t1x, t2x),
                 fminf(fmaxf(t1y, t2y), fmaxf(t1z, t2z)));
    bool hit = tmin < tmax;
    float t0 = fmaxf(hit ? tmin : 0.0f, 0.0f);

    // pos = campos + raydir*t0 : separate rn mul + rn add (knife edge)
    float posx = __fadd_rn(cx, __fmul_rn(dx, t0));
    float posy = __fadd_rn(cy, __fmul_rn(dy, t0));
    float posz = __fadd_rn(cz, __fmul_rn(dz, t0));

    // DT = 2^-5 => dir*DT is exact; per-step pos update is one rn add.
    float sx = dx * DT, sy = dy * DT, sz = dz * DT;

    float accR = 0.0f, accG = 0.0f, accB = 0.0f, accA = 0.0f;

    if (hit) {
        const uint4* __restrict__ volb = g_vol + (size_t)b * VOXELS;
        bool wasValid = false;

        #pragma unroll 1
        for (int it = 0; it < NSTEPS / 3; ++it) {        // 37 triples = 111
            // Sequential rn position chain (bit-identical to reference).
            float pbx = posx + sx, pby = posy + sy, pbz = posz + sz;
            float pcx = pbx + sx,  pcy = pby + sy,  pcz = pbz + sz;

            bool validA = (posx > -1.0f) & (posx < 1.0f) &
                          (posy > -1.0f) & (posy < 1.0f) &
                          (posz > -1.0f) & (posz < 1.0f);
            // Convex cube: once inside then outside, never inside again.
            if (wasValid & !validA) break;
            bool validB = (pbx > -1.0f) & (pbx < 1.0f) &
                          (pby > -1.0f) & (pby < 1.0f) &
                          (pbz > -1.0f) & (pbz < 1.0f);
            bool validC = (pcx > -1.0f) & (pcx < 1.0f) &
                          (pcy > -1.0f) & (pcy < 1.0f) &
                          (pcz > -1.0f) & (pcz < 1.0f);

            int xa, ya, za2, xb, yb, zb2, xc, yc, zc2;
            float fxa, fya, fza, fxb, fyb, fzb, fxc, fyc, fzc;
            coord(posx, xa, fxa); coord(posy, ya, fya); coord(posz, za2, fza);
            coord(pbx, xb, fxb);  coord(pby, yb, fyb);  coord(pbz, zb2, fzb);
            coord(pcx, xc, fxc);  coord(pcy, yc, fyc);  coord(pcz, zc2, fzc);

            int baseA = (((za2 << 7) + ya) << 7) + xa;
            int baseB = (((zb2 << 7) + yb) << 7) + xb;
            int baseC = (((zc2 << 7) + yc) << 7) + xc;

            // --- 12 loads for all three steps, issued together ---
            uint4 a00 = __ldg(volb + baseA);
            uint4 a01 = __ldg(volb + baseA + DVOX);
            uint4 a10 = __ldg(volb + baseA + DVOX * DVOX);
            uint4 a11 = __ldg(volb + baseA + DVOX * DVOX + DVOX);
            uint4 b00 = __ldg(volb + baseB);
            uint4 b01 = __ldg(volb + baseB + DVOX);
            uint4 b10 = __ldg(volb + baseB + DVOX * DVOX);
            uint4 b11 = __ldg(volb + baseB + DVOX * DVOX + DVOX);
            uint4 c00 = __ldg(volb + baseC);
            uint4 c01 = __ldg(volb + baseC + DVOX);
            uint4 c10 = __ldg(volb + baseC + DVOX * DVOX);
            uint4 c11 = __ldg(volb + baseC + DVOX * DVOX + DVOX);

            {
                float4 smp = trilerp(a00, a01, a10, a11, fxa, fya, fza);
                float va = validA ? 1.0f : 0.0f;
                float contrib = (fminf(accA + smp.w * DT, 1.0f) - accA) * va;
                accR += smp.x * contrib;
                accG += smp.y * contrib;
                accB += smp.z * contrib;
                accA += contrib;
            }
            {
                float4 smp = trilerp(b00, b01, b10, b11, fxb, fyb, fzb);
                float vb = validB ? 1.0f : 0.0f;
                float contrib = (fminf(accA + smp.w * DT, 1.0f) - accA) * vb;
                accR += smp.x * contrib;
                accG += smp.y * contrib;
                accB += smp.z * contrib;
                accA += contrib;
            }
            {
                float4 smp = trilerp(c00, c01, c10, c11, fxc, fyc, fzc);
                float vc = validC ? 1.0f : 0.0f;
                float contrib = (fminf(accA + smp.w * DT, 1.0f) - accA) * vc;
                accR += smp.x * contrib;
                accG += smp.y * contrib;
                accB += smp.z * contrib;
                accA += contrib;
            }

            // volume >= 0: alpha saturates to exactly 1.0, contrib 0 forever.
            if (accA >= 1.0f) break;
            wasValid |= (validA | validB | validC);

            posx = pcx + sx;
            posy = pcy + sy;
            posz = pcz + sz;
        }
    }

    // out: [B,4,H,W]
    int o = ((b * 4) * HPIX + h) * WPIX + w;
    const int CS = HPIX * WPIX;
    out[o]          = accR;
    out[o + CS]     = accG;
    out[o + 2 * CS] = accB;
    out[o + 3 * CS] = accA;
}

extern "C" void kernel_launch(void* const* d_in, const int* in_sizes, int n_in,
                              void* d_out, int out_size)
{
    const float* camrot      = (const float*)d_in[0];
    const float* campos      = (const float*)d_in[1];
    const float* focal       = (const float*)d_in[2];
    const float* princpt     = (const float*)d_in[3];
    const float* pixelcoords = (const float*)d_in[4];
    const float* volume      = (const float*)d_in[5];
    float* out = (float*)d_out;

    int B = in_sizes[1] / 3;                       // = 2
    int nrows = B * DVOX * DVOX;                   // one block per x-row
    interleave_kernel<<<nrows, DVOX>>>(volume);

    int npix = B * HPIX * WPIX;                    // 131072
    raymarch_kernel<<<npix / 128, 128>>>(camrot, campos, focal, princpt,
                                         pixelcoords, out);
}